// round 1
// baseline (speedup 1.0000x reference)
#include <cuda_runtime.h>
#include <math.h>

#define B_ 32
#define S_ 128
#define I_ 1024
#define H_ 1024
#define E_ 1024
#define V_ 32000

typedef unsigned long long u64;

// ---------------- scratch (__device__ globals; no runtime allocs) ----------------
__device__ __align__(16) float g_xTp[I_*B_];     // [I/2][B][2] pair-major transpose of x
__device__ __align__(16) float g_hTp[H_*B_];     // [H/2][B][2]
__device__ __align__(16) float g_decT[H_*B_];    // [H][B]
__device__ __align__(16) float g_vpart[8*B_*E_]; // [hc][B][E]
__device__ __align__(16) float g_v[B_*E_];       // [B][E]
__device__ __align__(16) float g_scores[B_*S_];
__device__ __align__(16) float g_attw[B_*S_];
__device__ __align__(16) float g_ctxTp[E_*B_];   // [E/2][B][2]
__device__ __align__(16) float g_combTp[I_*B_];  // [I/2][B][2]
__device__ __align__(16) float g_logits[B_*V_];  // [B][V] b-major
__device__ float g_pm[B_*8];
__device__ float g_ps[B_*8];

// ---------------- f32x2 helpers ----------------
#define FMA2(acc,a,b) asm("fma.rn.f32x2 %0, %1, %2, %0;" : "+l"(acc) : "l"(a), "l"(b))

__device__ __forceinline__ float hadd2(u64 v){
    float a, b;
    asm("mov.b64 {%0,%1}, %2;" : "=f"(a), "=f"(b) : "l"(v));
    return a + b;
}
__device__ __forceinline__ u64 d2u(double d){ return (u64)__double_as_longlong(d); }

// ---------------- 1) transpose x,hidden into pair-major [k/2][b][2] ----------------
__global__ void k_transpose(const float* __restrict__ x, const float* __restrict__ h){
    int idx = blockIdx.x * blockDim.x + threadIdx.x;   // 0..65535
    int which = idx >> 15;
    int r = idx & 32767;
    int b = r >> 10, k = r & 1023;
    float val = which ? h[r] : x[r];
    float* dst = which ? g_hTp : g_xTp;
    dst[(k >> 1) * 64 + b * 2 + (k & 1)] = val;
}

// ---------------- 2) fused GRU step -> decT[H][B] ----------------
__global__ void __launch_bounds__(256) k_gru(
    const float* __restrict__ Wih, const float* __restrict__ Whh,
    const float* __restrict__ bih, const float* __restrict__ bhh)
{
    int warp = threadIdx.x >> 5;
    int lane = threadIdx.x & 31;            // lane = batch
    int h = blockIdx.x * 8 + warp;

    const double2* wr = (const double2*)(Wih + (size_t)h * 1024);
    const double2* wz = (const double2*)(Wih + (size_t)(h + 1024) * 1024);
    const double2* wn = (const double2*)(Wih + (size_t)(h + 2048) * 1024);
    const double2* ur = (const double2*)(Whh + (size_t)h * 1024);
    const double2* uz = (const double2*)(Whh + (size_t)(h + 1024) * 1024);
    const double2* un = (const double2*)(Whh + (size_t)(h + 2048) * 1024);
    const u64* xp = (const u64*)g_xTp;
    const u64* hp = (const u64*)g_hTp;

    u64 axr = 0, axz = 0, axn = 0, ahr = 0, ahz = 0, ahn = 0;

    #pragma unroll 4
    for (int kq = 0; kq < 256; kq++) {
        u64 x0 = xp[kq * 64 + lane];
        u64 x1 = xp[kq * 64 + 32 + lane];
        u64 h0 = hp[kq * 64 + lane];
        u64 h1 = hp[kq * 64 + 32 + lane];

        double2 a;
        a = wr[kq]; FMA2(axr, d2u(a.x), x0); FMA2(axr, d2u(a.y), x1);
        a = wz[kq]; FMA2(axz, d2u(a.x), x0); FMA2(axz, d2u(a.y), x1);
        a = wn[kq]; FMA2(axn, d2u(a.x), x0); FMA2(axn, d2u(a.y), x1);
        a = ur[kq]; FMA2(ahr, d2u(a.x), h0); FMA2(ahr, d2u(a.y), h1);
        a = uz[kq]; FMA2(ahz, d2u(a.x), h0); FMA2(ahz, d2u(a.y), h1);
        a = un[kq]; FMA2(ahn, d2u(a.x), h0); FMA2(ahn, d2u(a.y), h1);
    }

    float xr = hadd2(axr) + bih[h];
    float xz = hadd2(axz) + bih[1024 + h];
    float xn = hadd2(axn) + bih[2048 + h];
    float hr = hadd2(ahr) + bhh[h];
    float hz = hadd2(ahz) + bhh[1024 + h];
    float hn = hadd2(ahn) + bhh[2048 + h];

    float r = 1.0f / (1.0f + expf(-(xr + hr)));
    float z = 1.0f / (1.0f + expf(-(xz + hz)));
    float n = tanhf(xn + r * hn);

    const float2* hp2 = (const float2*)g_hTp;
    float2 hpair = hp2[(h >> 1) * 32 + lane];
    float h0b = (h & 1) ? hpair.y : hpair.x;

    float dec = (1.0f - z) * n + z * h0b;
    g_decT[h * 32 + lane] = dec;
}

// ---------------- 3) v partial: v[b,e] += sum_h dec[b,h]*W_attn[h,1024+e] ----------------
__global__ void __launch_bounds__(128) k_vpart(const float* __restrict__ Wattn){
    int warp = threadIdx.x >> 5;
    int lane = threadIdx.x & 31;              // lane = batch
    int et = (blockIdx.x * 4 + warp) * 16;    // e tile base (0..1008)
    int hbase = blockIdx.y * 128;

    float acc[16];
    #pragma unroll
    for (int j = 0; j < 16; j++) acc[j] = 0.0f;

    for (int hh = 0; hh < 128; hh++) {
        int h = hbase + hh;
        float d = g_decT[h * 32 + lane];
        const float4* wrow = (const float4*)(Wattn + (size_t)h * 2048 + 1024 + et);
        float4 w0 = wrow[0], w1 = wrow[1], w2 = wrow[2], w3 = wrow[3];
        acc[0]  += d * w0.x; acc[1]  += d * w0.y; acc[2]  += d * w0.z; acc[3]  += d * w0.w;
        acc[4]  += d * w1.x; acc[5]  += d * w1.y; acc[6]  += d * w1.z; acc[7]  += d * w1.w;
        acc[8]  += d * w2.x; acc[9]  += d * w2.y; acc[10] += d * w2.z; acc[11] += d * w2.w;
        acc[12] += d * w3.x; acc[13] += d * w3.y; acc[14] += d * w3.z; acc[15] += d * w3.w;
    }
    float4* dst = (float4*)(g_vpart + ((size_t)blockIdx.y * 32 + lane) * 1024 + et);
    dst[0] = make_float4(acc[0],  acc[1],  acc[2],  acc[3]);
    dst[1] = make_float4(acc[4],  acc[5],  acc[6],  acc[7]);
    dst[2] = make_float4(acc[8],  acc[9],  acc[10], acc[11]);
    dst[3] = make_float4(acc[12], acc[13], acc[14], acc[15]);
}

// ---------------- 4) v reduce over 8 h-chunks ----------------
__global__ void k_vreduce(){
    int idx = blockIdx.x * 1024 + threadIdx.x;   // 0..32767
    float s = 0.0f;
    #pragma unroll
    for (int c = 0; c < 8; c++) s += g_vpart[c * (B_*E_) + idx];
    g_v[idx] = s;
}

// ---------------- 5) scores[b,s] = enc[s,b,:] . v[b,:] ----------------
__global__ void __launch_bounds__(128) k_scores(const float* __restrict__ enc){
    int g = blockIdx.x * 4 + (threadIdx.x >> 5);   // 0..4095
    int lane = threadIdx.x & 31;
    int b = g & 31, s = g >> 5;
    const float4* ep = (const float4*)(enc + (size_t)(s * 32 + b) * 1024);
    const float4* vp = (const float4*)(g_v + b * 1024);
    float acc = 0.0f;
    #pragma unroll
    for (int i = 0; i < 8; i++) {
        float4 e4 = ep[i * 32 + lane];
        float4 v4 = vp[i * 32 + lane];
        acc += e4.x * v4.x + e4.y * v4.y + e4.z * v4.z + e4.w * v4.w;
    }
    #pragma unroll
    for (int off = 16; off; off >>= 1) acc += __shfl_xor_sync(0xFFFFFFFFu, acc, off);
    if (lane == 0) g_scores[b * 128 + s] = acc;
}

// ---------------- 6) softmax over s; write attn weights to out tail ----------------
__global__ void k_softmax(float* __restrict__ out){
    int b = blockIdx.x, s = threadIdx.x;
    float x = g_scores[b * 128 + s];
    __shared__ float red[128];
    red[s] = x; __syncthreads();
    for (int st = 64; st > 0; st >>= 1) { if (s < st) red[s] = fmaxf(red[s], red[s + st]); __syncthreads(); }
    float m = red[0]; __syncthreads();
    float e = expf(x - m);
    red[s] = e; __syncthreads();
    for (int st = 64; st > 0; st >>= 1) { if (s < st) red[s] += red[s + st]; __syncthreads(); }
    float w = e / red[0];
    g_attw[b * 128 + s] = w;
    out[(size_t)B_ * V_ + b * 128 + s] = w;
}

// ---------------- 7) context[b,e] = sum_s w[b,s]*enc[s,b,e] -> ctxTp pairs ----------------
__global__ void __launch_bounds__(256) k_context(const float* __restrict__ enc){
    int b = blockIdx.x;
    __shared__ float ws[128];
    if (threadIdx.x < 128) ws[threadIdx.x] = g_attw[b * 128 + threadIdx.x];
    __syncthreads();
    int e0 = threadIdx.x * 4;
    const float* encb = enc + (size_t)b * 1024 + e0;
    float4 acc = make_float4(0.f, 0.f, 0.f, 0.f);
    #pragma unroll 4
    for (int s = 0; s < 128; s++) {
        float4 t = *(const float4*)(encb + (size_t)s * (B_*E_));
        float w = ws[s];
        acc.x += w * t.x; acc.y += w * t.y; acc.z += w * t.z; acc.w += w * t.w;
    }
    float2* dst = (float2*)g_ctxTp;
    int kp0 = e0 >> 1;
    dst[kp0 * 32 + b]       = make_float2(acc.x, acc.y);
    dst[(kp0 + 1) * 32 + b] = make_float2(acc.z, acc.w);
}

// ---------------- 8) comb[b,i] = [x,ctx] @ W_comb[i,:] + b_comb -> combTp ----------------
__global__ void __launch_bounds__(256) k_comb(
    const float* __restrict__ Wcomb, const float* __restrict__ bcomb)
{
    int warp = threadIdx.x >> 5;
    int lane = threadIdx.x & 31;
    int i = blockIdx.x * 8 + warp;   // output row 0..1023

    const double2* wx = (const double2*)(Wcomb + (size_t)i * 2048);
    const double2* wc = wx + 256;    // +1024 floats
    const u64* xp = (const u64*)g_xTp;
    const u64* cp = (const u64*)g_ctxTp;

    u64 acc = 0;
    #pragma unroll 4
    for (int kq = 0; kq < 256; kq++) {
        double2 a = wx[kq];
        u64 x0 = xp[kq * 64 + lane];
        u64 x1 = xp[kq * 64 + 32 + lane];
        FMA2(acc, d2u(a.x), x0); FMA2(acc, d2u(a.y), x1);
        double2 c = wc[kq];
        u64 c0 = cp[kq * 64 + lane];
        u64 c1 = cp[kq * 64 + 32 + lane];
        FMA2(acc, d2u(c.x), c0); FMA2(acc, d2u(c.y), c1);
    }
    float v = hadd2(acc) + bcomb[i];
    g_combTp[(i >> 1) * 64 + lane * 2 + (i & 1)] = v;
}

// ---------------- 9) logits[b,v] = comb @ W_out^T + b_out (f32x2 K-packed GEMM) ----------------
__global__ void __launch_bounds__(128) k_gemm(
    const float* __restrict__ Wout, const float* __restrict__ bout)
{
    __shared__ float Ws[16][128];   // [kpair][v*2 + half], 64 v rows
    __shared__ float Us[16][64];    // [kpair][b*2 + half], 32 b

    int tid = threadIdx.x;
    int i = tid & 15;  int v0 = i * 4;
    int j = tid >> 4;  int b0 = j * 4;
    int vbase = blockIdx.x * 64;

    u64 acc[4][4];
    #pragma unroll
    for (int r = 0; r < 4; r++)
        #pragma unroll
        for (int c = 0; c < 4; c++) acc[r][c] = 0;

    for (int kt = 0; kt < 32; kt++) {
        __syncthreads();
        {   // stage W tile 64x32 -> pair-major smem
            int row = tid >> 1, seg = tid & 1;
            const float4* src = (const float4*)(Wout + (size_t)(vbase + row) * 1024 + kt * 32 + seg * 16);
            #pragma unroll
            for (int q = 0; q < 4; q++) {
                float4 w = src[q];
                int kp = seg * 8 + q * 2;
                *(float2*)&Ws[kp][row * 2]     = make_float2(w.x, w.y);
                *(float2*)&Ws[kp + 1][row * 2] = make_float2(w.z, w.w);
            }
        }
        {   // stage U tile (already pair-major in combTp)
            const float4* src = (const float4*)(g_combTp + kt * 1024);
            ((float4*)Us)[tid]       = src[tid];
            ((float4*)Us)[tid + 128] = src[tid + 128];
        }
        __syncthreads();

        #pragma unroll
        for (int kp = 0; kp < 16; kp++) {
            double2 dA = *(const double2*)&Ws[kp][v0 * 2];
            double2 dB = *(const double2*)&Ws[kp][v0 * 2 + 4];
            double2 uA = *(const double2*)&Us[kp][b0 * 2];
            double2 uB = *(const double2*)&Us[kp][b0 * 2 + 4];
            u64 w0 = d2u(dA.x), w1 = d2u(dA.y), w2 = d2u(dB.x), w3 = d2u(dB.y);
            u64 u0 = d2u(uA.x), u1 = d2u(uA.y), u2 = d2u(uB.x), u3 = d2u(uB.y);
            FMA2(acc[0][0], w0, u0); FMA2(acc[0][1], w0, u1); FMA2(acc[0][2], w0, u2); FMA2(acc[0][3], w0, u3);
            FMA2(acc[1][0], w1, u0); FMA2(acc[1][1], w1, u1); FMA2(acc[1][2], w1, u2); FMA2(acc[1][3], w1, u3);
            FMA2(acc[2][0], w2, u0); FMA2(acc[2][1], w2, u1); FMA2(acc[2][2], w2, u2); FMA2(acc[2][3], w2, u3);
            FMA2(acc[3][0], w3, u0); FMA2(acc[3][1], w3, u1); FMA2(acc[3][2], w3, u2); FMA2(acc[3][3], w3, u3);
        }
    }

    #pragma unroll
    for (int r = 0; r < 4; r++) {
        int vr = vbase + v0 + r;
        float bb = bout[vr];
        #pragma unroll
        for (int c = 0; c < 4; c++) {
            float val = hadd2(acc[r][c]) + bb;
            g_logits[(size_t)(b0 + c) * V_ + vr] = val;
        }
    }
}

// ---------------- 10) log-softmax partial reduce (online max/sum) ----------------
__global__ void k_lsm_part(){
    int b = blockIdx.x, c = blockIdx.y;
    const float4* base = (const float4*)(g_logits + (size_t)b * V_ + c * 4000);
    float m = -3.4e38f, s = 0.0f;
    #pragma unroll
    for (int it = 0; it < 4; it++) {
        int idx = threadIdx.x + it * 256;
        if (idx < 1000) {
            float4 x = base[idx];
            float mx = fmaxf(fmaxf(x.x, x.y), fmaxf(x.z, x.w));
            if (mx > m) { s = s * expf(m - mx); m = mx; }
            s += expf(x.x - m) + expf(x.y - m) + expf(x.z - m) + expf(x.w - m);
        }
    }
    __shared__ float sm[256], ss[256];
    sm[threadIdx.x] = m; ss[threadIdx.x] = s;
    __syncthreads();
    for (int st = 128; st > 0; st >>= 1) {
        if (threadIdx.x < st) {
            float m2 = sm[threadIdx.x + st], s2 = ss[threadIdx.x + st];
            float mo = fmaxf(sm[threadIdx.x], m2);
            ss[threadIdx.x] = ss[threadIdx.x] * expf(sm[threadIdx.x] - mo) + s2 * expf(m2 - mo);
            sm[threadIdx.x] = mo;
        }
        __syncthreads();
    }
    if (threadIdx.x == 0) { g_pm[b * 8 + c] = sm[0]; g_ps[b * 8 + c] = ss[0]; }
}

// ---------------- 11) log-softmax finalize + write ----------------
__global__ void k_lsm_write(float* __restrict__ out){
    int b = blockIdx.x;
    float M = -3.4e38f;
    #pragma unroll
    for (int c = 0; c < 8; c++) M = fmaxf(M, g_pm[b * 8 + c]);
    float Ssum = 0.0f;
    #pragma unroll
    for (int c = 0; c < 8; c++) Ssum += g_ps[b * 8 + c] * expf(g_pm[b * 8 + c] - M);
    float off = M + logf(Ssum);

    int chunk = blockIdx.y * 2000;
    const float4* src = (const float4*)(g_logits + (size_t)b * V_ + chunk);
    float4* dst = (float4*)(out + (size_t)b * V_ + chunk);
    #pragma unroll
    for (int it = 0; it < 2; it++) {
        int idx = threadIdx.x + it * 256;
        if (idx < 500) {
            float4 x = src[idx];
            dst[idx] = make_float4(x.x - off, x.y - off, x.z - off, x.w - off);
        }
    }
}

// ---------------- launch ----------------
extern "C" void kernel_launch(void* const* d_in, const int* in_sizes, int n_in,
                              void* d_out, int out_size)
{
    const float* x     = (const float*)d_in[0];
    const float* enc   = (const float*)d_in[1];
    const float* hid   = (const float*)d_in[2];
    const float* Wih   = (const float*)d_in[3];
    const float* Whh   = (const float*)d_in[4];
    const float* bih   = (const float*)d_in[5];
    const float* bhh   = (const float*)d_in[6];
    const float* Wattn = (const float*)d_in[7];
    // d_in[8] = b_attn: provably softmax-invariant, unused
    const float* Wcomb = (const float*)d_in[9];
    const float* bcomb = (const float*)d_in[10];
    const float* Wout  = (const float*)d_in[11];
    const float* bout  = (const float*)d_in[12];
    float* out = (float*)d_out;

    k_transpose<<<128, 512>>>(x, hid);
    k_gru<<<128, 256>>>(Wih, Whh, bih, bhh);
    k_vpart<<<dim3(16, 8), 128>>>(Wattn);
    k_vreduce<<<32, 1024>>>();
    k_scores<<<1024, 128>>>(enc);
    k_softmax<<<32, 128>>>(out);
    k_context<<<32, 256>>>(enc);
    k_comb<<<128, 256>>>(Wcomb, bcomb);
    k_gemm<<<500, 128>>>(Wout, bout);
    k_lsm_part<<<dim3(32, 8), 256>>>();
    k_lsm_write<<<dim3(32, 16), 256>>>(out);
}

// round 2
// speedup vs baseline: 1.7221x; 1.7221x over previous
#include <cuda_runtime.h>
#include <math.h>

#define B_ 32
#define S_ 128
#define I_ 1024
#define H_ 1024
#define E_ 1024
#define V_ 32000

typedef unsigned long long u64;

// ---------------- scratch ----------------
__device__ __align__(16) float g_combU[2048*32];   // rows 0-1023: xT[k][b]; 1024-2047: ctxT[e][b]
__device__ __align__(16) float g_hT[1024*32];      // hT[k][b]
__device__ __align__(16) float g_xgP[4*3072*32];   // GRU x-gate partials [split][v][b]
__device__ __align__(16) float g_hgP[4*3072*32];   // GRU h-gate partials
__device__ __align__(16) float g_decT[1024*32];    // dec [h][b]
__device__ __align__(16) float g_vP[8*1024*32];    // v partials [split][e][b]
__device__ __align__(16) float g_v[32*1024];       // v [b][e]
__device__ __align__(16) float g_scores[32*128];
__device__ __align__(16) float g_attw[32*128];
__device__ __align__(16) float g_ctxP[4*1024*32];  // context partials [ssplit][e][b]
__device__ __align__(16) float g_combP[8*1024*32]; // comb partials [split][i][b]
__device__ __align__(16) float g_outU[1024*32];    // comb result [k][b] (U for W_out gemm)
__device__ __align__(16) float g_logits[32*32000]; // [b][v]
__device__ float g_pm[32*8];
__device__ float g_ps[32*8];

// ---------------- f32x2 helpers ----------------
#define FMA2(acc,a,b) asm("fma.rn.f32x2 %0, %1, %2, %0;" : "+l"(acc) : "l"(a), "l"(b))

__device__ __forceinline__ u64 dup2(float w){
    u64 r; asm("mov.b64 %0, {%1, %1};" : "=l"(r) : "f"(w)); return r;
}
__device__ __forceinline__ u64 d2u(double d){ return (u64)__double_as_longlong(d); }
__device__ __forceinline__ void unpk(u64 v, float& a, float& b){
    asm("mov.b64 {%0,%1}, %2;" : "=f"(a), "=f"(b) : "l"(v));
}

// inner: one k; wd = (w,w); Usk points at U[k][0..31] in smem (broadcast)
__device__ __forceinline__ void inner_k(u64 wd, const float* Usk, u64 acc[16]){
    #pragma unroll
    for (int p = 0; p < 16; p += 2) {
        double2 u2 = *(const double2*)(Usk + 2*p);   // broadcast LDS.128: U[k][2p..2p+3]
        FMA2(acc[p],   wd, d2u(u2.x));
        FMA2(acc[p+1], wd, d2u(u2.y));
    }
}

__device__ __forceinline__ void stageU(float* Us, const float* Ug, int nfloats){
    const float4* s = (const float4*)Ug;
    float4* d = (float4*)Us;
    for (int i = threadIdx.x; i < nfloats/4; i += blockDim.x) d[i] = s[i];
    __syncthreads();
}

// ---------------- 1) transpose x -> combU[0:1024], h -> hT ----------------
__global__ void k_prep(const float* __restrict__ x, const float* __restrict__ h){
    int idx = blockIdx.x * blockDim.x + threadIdx.x;  // 0..65535
    int which = idx >> 15;
    int r = idx & 32767;
    int i = r >> 5, b = r & 31;
    if (which == 0) g_combU[i*32 + b] = x[b*1024 + i];
    else            g_hT[i*32 + b]    = h[b*1024 + i];
}

// ---------------- 2) GRU gemms: xgP/hgP partials ----------------
// grid (12 vblocks, 4 ksplits, 2 mats), 256 thr
__global__ void __launch_bounds__(256) k_gru_gemm(
    const float* __restrict__ Wih, const float* __restrict__ Whh)
{
    __shared__ float Us[256*32];
    int split = blockIdx.y, z = blockIdx.z;
    const float* W  = z ? Whh   : Wih;
    const float* Ug = z ? g_hT  : g_combU;
    float* P        = z ? g_hgP : g_xgP;
    int k0 = split * 256;
    stageU(Us, Ug + (size_t)k0*32, 256*32);

    int warp = threadIdx.x >> 5, lane = threadIdx.x & 31;
    int v = blockIdx.x*256 + warp*32 + lane;         // 0..3071
    const float4* w4 = (const float4*)(W + (size_t)v*1024 + k0);

    u64 acc[16];
    #pragma unroll
    for (int p = 0; p < 16; p++) acc[p] = 0;

    #pragma unroll 2
    for (int kk = 0; kk < 64; kk++){
        float4 w = w4[kk];
        inner_k(dup2(w.x), Us + (kk*4+0)*32, acc);
        inner_k(dup2(w.y), Us + (kk*4+1)*32, acc);
        inner_k(dup2(w.z), Us + (kk*4+2)*32, acc);
        inner_k(dup2(w.w), Us + (kk*4+3)*32, acc);
    }
    float* o = P + ((size_t)split*3072 + v)*32;
    #pragma unroll
    for (int p = 0; p < 16; p++){
        float lo, hi; unpk(acc[p], lo, hi);
        *(float2*)(o + 2*p) = make_float2(lo, hi);
    }
}

// ---------------- 3) GRU activation -> decT[h][b] ----------------
__global__ void k_gru_act(const float* __restrict__ bih, const float* __restrict__ bhh){
    int idx = blockIdx.x*256 + threadIdx.x;  // 32768
    int h = idx >> 5, b = idx & 31;
    float xr=0, xz=0, xn=0, hr=0, hz=0, hn=0;
    #pragma unroll
    for (int s = 0; s < 4; s++){
        size_t base = (size_t)s*3072*32;
        xr += g_xgP[base + (size_t)h*32 + b];
        xz += g_xgP[base + (size_t)(1024+h)*32 + b];
        xn += g_xgP[base + (size_t)(2048+h)*32 + b];
        hr += g_hgP[base + (size_t)h*32 + b];
        hz += g_hgP[base + (size_t)(1024+h)*32 + b];
        hn += g_hgP[base + (size_t)(2048+h)*32 + b];
    }
    xr += bih[h]; xz += bih[1024+h]; xn += bih[2048+h];
    hr += bhh[h]; hz += bhh[1024+h]; hn += bhh[2048+h];
    float r = 1.0f / (1.0f + expf(-(xr + hr)));
    float z = 1.0f / (1.0f + expf(-(xz + hz)));
    float n = tanhf(xn + r*hn);
    float h0 = g_hT[h*32 + b];
    g_decT[h*32 + b] = (1.0f - z)*n + z*h0;
}

// ---------------- 4) v gemm: vP[split][e][b] = sum_h Wa2[h][e]*dec[h][b] ----------------
// grid (4 eblocks, 8 hsplits), 256 thr; W lane-coalesced (e contiguous)
__global__ void __launch_bounds__(256) k_v_gemm(const float* __restrict__ Wattn){
    __shared__ float Us[128*32];
    int split = blockIdx.y;
    int k0 = split * 128;
    stageU(Us, g_decT + (size_t)k0*32, 128*32);

    int warp = threadIdx.x >> 5, lane = threadIdx.x & 31;
    int e = blockIdx.x*256 + warp*32 + lane;
    const float* wp = Wattn + (size_t)k0*2048 + 1024 + e;

    u64 acc[16];
    #pragma unroll
    for (int p = 0; p < 16; p++) acc[p] = 0;

    #pragma unroll 4
    for (int k = 0; k < 128; k++){
        float w = wp[(size_t)k*2048];
        inner_k(dup2(w), Us + k*32, acc);
    }
    float* o = g_vP + ((size_t)split*1024 + e)*32;
    #pragma unroll
    for (int p = 0; p < 16; p++){
        float lo, hi; unpk(acc[p], lo, hi);
        *(float2*)(o + 2*p) = make_float2(lo, hi);
    }
}

// ---------------- 5) v reduce -> g_v[b][e] ----------------
__global__ void k_v_red(){
    int idx = blockIdx.x*1024 + threadIdx.x;  // 32768
    int e = idx >> 5, b = idx & 31;
    float s = 0.0f;
    #pragma unroll
    for (int c = 0; c < 8; c++) s += g_vP[(size_t)c*32768 + e*32 + b];
    g_v[b*1024 + e] = s;
}

// ---------------- 6) scores[b,s] = enc[s,b,:] . v[b,:] ----------------
__global__ void __launch_bounds__(128) k_scores(const float* __restrict__ enc){
    int g = blockIdx.x * 4 + (threadIdx.x >> 5);
    int lane = threadIdx.x & 31;
    int b = g & 31, s = g >> 5;
    const float4* ep = (const float4*)(enc + (size_t)(s*32 + b)*1024);
    const float4* vp = (const float4*)(g_v + b*1024);
    float acc = 0.0f;
    #pragma unroll
    for (int i = 0; i < 8; i++){
        float4 e4 = ep[i*32 + lane];
        float4 v4 = vp[i*32 + lane];
        acc += e4.x*v4.x + e4.y*v4.y + e4.z*v4.z + e4.w*v4.w;
    }
    #pragma unroll
    for (int off = 16; off; off >>= 1) acc += __shfl_xor_sync(0xFFFFFFFFu, acc, off);
    if (lane == 0) g_scores[b*128 + s] = acc;
}

// ---------------- 7) softmax over s ----------------
__global__ void k_softmax(float* __restrict__ out){
    int b = blockIdx.x, s = threadIdx.x;
    float x = g_scores[b*128 + s];
    __shared__ float red[128];
    red[s] = x; __syncthreads();
    for (int st = 64; st > 0; st >>= 1){ if (s < st) red[s] = fmaxf(red[s], red[s+st]); __syncthreads(); }
    float m = red[0]; __syncthreads();
    float e = expf(x - m);
    red[s] = e; __syncthreads();
    for (int st = 64; st > 0; st >>= 1){ if (s < st) red[s] += red[s+st]; __syncthreads(); }
    float w = e / red[0];
    g_attw[b*128 + s] = w;
    out[(size_t)B_*V_ + b*128 + s] = w;
}

// ---------------- 8) context partials: ctxP[ss][e][b] ----------------
// grid (32 b, 4 e-chunks, 4 s-splits), 256 thr (thread = e)
__global__ void __launch_bounds__(256) k_context(const float* __restrict__ enc){
    int b = blockIdx.x, ec = blockIdx.y, ss = blockIdx.z;
    __shared__ float ws[32];
    if (threadIdx.x < 32) ws[threadIdx.x] = g_attw[b*128 + ss*32 + threadIdx.x];
    __syncthreads();
    int e = ec*256 + threadIdx.x;
    const float* ep = enc + ((size_t)(ss*32)*32 + b)*1024 + e;
    float acc = 0.0f;
    #pragma unroll 4
    for (int s = 0; s < 32; s++) acc += ws[s] * ep[(size_t)s*32768];
    g_ctxP[((size_t)ss*1024 + e)*32 + b] = acc;
}

// ---------------- 9) ctx reduce -> combU[1024+e][b] ----------------
__global__ void k_ctx_red(){
    int idx = blockIdx.x*1024 + threadIdx.x;  // 32768
    int e = idx >> 5, b = idx & 31;
    float s = 0.0f;
    #pragma unroll
    for (int c = 0; c < 4; c++) s += g_ctxP[(size_t)c*32768 + e*32 + b];
    g_combU[(size_t)(1024 + e)*32 + b] = s;
}

// ---------------- 10) comb gemm: combP[split][i][b] ----------------
// grid (4 vblocks, 8 ksplits), 256 thr; K=2048
__global__ void __launch_bounds__(256) k_comb_gemm(const float* __restrict__ Wcomb){
    __shared__ float Us[256*32];
    int split = blockIdx.y;
    int k0 = split * 256;
    stageU(Us, g_combU + (size_t)k0*32, 256*32);

    int warp = threadIdx.x >> 5, lane = threadIdx.x & 31;
    int v = blockIdx.x*256 + warp*32 + lane;  // 0..1023
    const float4* w4 = (const float4*)(Wcomb + (size_t)v*2048 + k0);

    u64 acc[16];
    #pragma unroll
    for (int p = 0; p < 16; p++) acc[p] = 0;

    #pragma unroll 2
    for (int kk = 0; kk < 64; kk++){
        float4 w = w4[kk];
        inner_k(dup2(w.x), Us + (kk*4+0)*32, acc);
        inner_k(dup2(w.y), Us + (kk*4+1)*32, acc);
        inner_k(dup2(w.z), Us + (kk*4+2)*32, acc);
        inner_k(dup2(w.w), Us + (kk*4+3)*32, acc);
    }
    float* o = g_combP + ((size_t)split*1024 + v)*32;
    #pragma unroll
    for (int p = 0; p < 16; p++){
        float lo, hi; unpk(acc[p], lo, hi);
        *(float2*)(o + 2*p) = make_float2(lo, hi);
    }
}

// ---------------- 11) comb reduce + bias -> outU[k][b] ----------------
__global__ void k_comb_red(const float* __restrict__ bcomb){
    int idx = blockIdx.x*1024 + threadIdx.x;  // 32768
    int k = idx >> 5, b = idx & 31;
    float s = bcomb[k];
    #pragma unroll
    for (int c = 0; c < 8; c++) s += g_combP[(size_t)c*32768 + k*32 + b];
    g_outU[k*32 + b] = s;
}

// ---------------- 12) W_out gemm -> g_logits[b][v] ----------------
// grid (125), 256 thr, 128KB dynamic smem
__global__ void __launch_bounds__(256) k_out_gemm(
    const float* __restrict__ Wout, const float* __restrict__ bout)
{
    extern __shared__ float Us[];  // 1024*32
    stageU(Us, g_outU, 1024*32);

    int warp = threadIdx.x >> 5, lane = threadIdx.x & 31;
    int v = blockIdx.x*256 + warp*32 + lane;  // 0..31999
    const float4* w4 = (const float4*)(Wout + (size_t)v*1024);

    u64 acc[16];
    #pragma unroll
    for (int p = 0; p < 16; p++) acc[p] = 0;

    #pragma unroll 2
    for (int kk = 0; kk < 256; kk++){
        float4 w = w4[kk];
        inner_k(dup2(w.x), Us + (kk*4+0)*32, acc);
        inner_k(dup2(w.y), Us + (kk*4+1)*32, acc);
        inner_k(dup2(w.z), Us + (kk*4+2)*32, acc);
        inner_k(dup2(w.w), Us + (kk*4+3)*32, acc);
    }
    float bb = bout[v];
    #pragma unroll
    for (int p = 0; p < 16; p++){
        float lo, hi; unpk(acc[p], lo, hi);
        g_logits[(size_t)(2*p  )*V_ + v] = lo + bb;
        g_logits[(size_t)(2*p+1)*V_ + v] = hi + bb;
    }
}

// ---------------- 13) log-softmax partial (online max/sum) ----------------
__global__ void k_lsm_part(){
    int b = blockIdx.x, c = blockIdx.y;
    const float4* base = (const float4*)(g_logits + (size_t)b*V_ + c*4000);
    float m = -3.4e38f, s = 0.0f;
    #pragma unroll
    for (int it = 0; it < 4; it++){
        int idx = threadIdx.x + it*256;
        if (idx < 1000){
            float4 x = base[idx];
            float mx = fmaxf(fmaxf(x.x, x.y), fmaxf(x.z, x.w));
            if (mx > m){ s = s * expf(m - mx); m = mx; }
            s += expf(x.x - m) + expf(x.y - m) + expf(x.z - m) + expf(x.w - m);
        }
    }
    __shared__ float sm[256], ss[256];
    sm[threadIdx.x] = m; ss[threadIdx.x] = s;
    __syncthreads();
    for (int st = 128; st > 0; st >>= 1){
        if (threadIdx.x < st){
            float m2 = sm[threadIdx.x + st], s2 = ss[threadIdx.x + st];
            float mo = fmaxf(sm[threadIdx.x], m2);
            ss[threadIdx.x] = ss[threadIdx.x]*expf(sm[threadIdx.x] - mo) + s2*expf(m2 - mo);
            sm[threadIdx.x] = mo;
        }
        __syncthreads();
    }
    if (threadIdx.x == 0){ g_pm[b*8 + c] = sm[0]; g_ps[b*8 + c] = ss[0]; }
}

// ---------------- 14) log-softmax finalize ----------------
__global__ void k_lsm_write(float* __restrict__ out){
    int b = blockIdx.x;
    float M = -3.4e38f;
    #pragma unroll
    for (int c = 0; c < 8; c++) M = fmaxf(M, g_pm[b*8 + c]);
    float Ssum = 0.0f;
    #pragma unroll
    for (int c = 0; c < 8; c++) Ssum += g_ps[b*8 + c] * expf(g_pm[b*8 + c] - M);
    float off = M + logf(Ssum);

    int chunk = blockIdx.y * 2000;
    const float4* src = (const float4*)(g_logits + (size_t)b*V_ + chunk);
    float4* dst = (float4*)(out + (size_t)b*V_ + chunk);
    #pragma unroll
    for (int it = 0; it < 2; it++){
        int idx = threadIdx.x + it*256;
        if (idx < 500){
            float4 x = src[idx];
            dst[idx] = make_float4(x.x - off, x.y - off, x.z - off, x.w - off);
        }
    }
}

// ---------------- launch ----------------
extern "C" void kernel_launch(void* const* d_in, const int* in_sizes, int n_in,
                              void* d_out, int out_size)
{
    const float* x     = (const float*)d_in[0];
    const float* enc   = (const float*)d_in[1];
    const float* hid   = (const float*)d_in[2];
    const float* Wih   = (const float*)d_in[3];
    const float* Whh   = (const float*)d_in[4];
    const float* bih   = (const float*)d_in[5];
    const float* bhh   = (const float*)d_in[6];
    const float* Wattn = (const float*)d_in[7];
    // d_in[8] = b_attn: softmax-invariant, unused
    const float* Wcomb = (const float*)d_in[9];
    const float* bcomb = (const float*)d_in[10];
    const float* Wout  = (const float*)d_in[11];
    const float* bout  = (const float*)d_in[12];
    float* out = (float*)d_out;

    static bool attr_set = false;
    if (!attr_set){
        cudaFuncSetAttribute(k_out_gemm, cudaFuncAttributeMaxDynamicSharedMemorySize, 1024*32*4);
        attr_set = true;
    }

    k_prep<<<128, 512>>>(x, hid);
    k_gru_gemm<<<dim3(12, 4, 2), 256>>>(Wih, Whh);
    k_gru_act<<<128, 256>>>(bih, bhh);
    k_v_gemm<<<dim3(4, 8), 256>>>(Wattn);
    k_v_red<<<32, 1024>>>();
    k_scores<<<1024, 128>>>(enc);
    k_softmax<<<32, 128>>>(out);
    k_context<<<dim3(32, 4, 4), 256>>>(enc);
    k_ctx_red<<<32, 1024>>>();
    k_comb_gemm<<<dim3(4, 8), 256>>>(Wcomb);
    k_comb_red<<<32, 1024>>>(bcomb);
    k_out_gemm<<<125, 256, 1024*32*4>>>(Wout, bout);
    k_lsm_part<<<dim3(32, 8), 256>>>();
    k_lsm_write<<<dim3(32, 16), 256>>>(out);
}

// round 3
// speedup vs baseline: 2.0257x; 1.1763x over previous
#include <cuda_runtime.h>
#include <math.h>

#define B_ 32
#define S_ 128
#define I_ 1024
#define H_ 1024
#define E_ 1024
#define V_ 32000

typedef unsigned long long u64;

// ---------------- scratch ----------------
__device__ __align__(16) float g_xgP[8*3072*32];   // GRU x-gate partials [split][v][b]
__device__ __align__(16) float g_hgP[8*3072*32];   // GRU h-gate partials
__device__ __align__(16) float g_decT[1024*32];    // dec [h][b]
__device__ __align__(16) float g_vP[32*1024*32];   // v partials [split][e][b]
__device__ __align__(16) float g_v[32*1024];       // v [b][e]
__device__ __align__(16) float g_scores[32*128];
__device__ __align__(16) float g_attw[32*128];
__device__ __align__(16) float g_ctx[1024*32];     // context [e][b]
__device__ __align__(16) float g_combP[16*1024*32];// comb partials [split][i][b]
__device__ __align__(16) float g_outU[1024*32];    // comb result [k][b]
__device__ __align__(16) float g_logits[32*32000]; // [b][v]
__device__ float g_pm[32*8];
__device__ float g_ps[32*8];

// ---------------- f32x2 helpers ----------------
#define FMA2(acc,a,b) asm("fma.rn.f32x2 %0, %1, %2, %0;" : "+l"(acc) : "l"(a), "l"(b))

__device__ __forceinline__ u64 dup2(float w){
    u64 r; asm("mov.b64 %0, {%1, %1};" : "=l"(r) : "f"(w)); return r;
}
__device__ __forceinline__ u64 d2u(double d){ return (u64)__double_as_longlong(d); }
__device__ __forceinline__ void unpk(u64 v, float& a, float& b){
    asm("mov.b64 {%0,%1}, %2;" : "=f"(a), "=f"(b) : "l"(v));
}

#define USTRIDE 36   // padded row stride (floats); 144B = 16B-aligned rows, conflict-friendly

// inner: one k; wd = (w,w); Usk = row pointer (broadcast LDS.128)
__device__ __forceinline__ void inner_k(u64 wd, const float* Usk, u64 acc[16]){
    #pragma unroll
    for (int p = 0; p < 16; p += 2) {
        double2 u2 = *(const double2*)(Usk + 2*p);
        FMA2(acc[p],   wd, d2u(u2.x));
        FMA2(acc[p+1], wd, d2u(u2.y));
    }
}

// stage k-major [kchunk][32] contiguous source into padded smem rows
__device__ __forceinline__ void stage_straight(float* Us, const float* src, int kchunk){
    int n4 = kchunk * 8;
    for (int idx = threadIdx.x; idx < n4; idx += blockDim.x){
        int k = idx >> 3, q = idx & 7;
        float4 v = ((const float4*)src)[idx];
        *(float4*)(Us + k*USTRIDE + q*4) = v;
    }
    __syncthreads();
}

// stage b-major source [32][1024] (cols k0..k0+kchunk) transposed into padded rows
template<int KCH>
__device__ __forceinline__ void stage_transpose(float* Us, const float* src, int k0){
    for (int idx = threadIdx.x; idx < 32*KCH; idx += blockDim.x){
        int b = idx / KCH, kk = idx % KCH;
        Us[kk*USTRIDE + b] = src[b*1024 + k0 + kk];
    }
    __syncthreads();
}

// ---------------- 1) GRU gemms (transpose-staging x/h) ----------------
// grid (12 vblocks, 8 ksplits, 2 mats), 256 thr
__global__ void __launch_bounds__(256) k_gru_gemm(
    const float* __restrict__ x, const float* __restrict__ hid,
    const float* __restrict__ Wih, const float* __restrict__ Whh)
{
    __shared__ float Us[128*USTRIDE];
    int split = blockIdx.y, z = blockIdx.z;
    const float* W  = z ? Whh : Wih;
    float* P        = z ? g_hgP : g_xgP;
    int k0 = split * 128;
    stage_transpose<128>(Us, z ? hid : x, k0);

    int warp = threadIdx.x >> 5, lane = threadIdx.x & 31;
    int v = blockIdx.x*256 + warp*32 + lane;     // 0..3071
    const float4* w4 = (const float4*)(W + (size_t)v*1024 + k0);

    u64 acc[16];
    #pragma unroll
    for (int p = 0; p < 16; p++) acc[p] = 0;

    #pragma unroll 4
    for (int kk = 0; kk < 32; kk++){
        float4 w = w4[kk];
        inner_k(dup2(w.x), Us + (kk*4+0)*USTRIDE, acc);
        inner_k(dup2(w.y), Us + (kk*4+1)*USTRIDE, acc);
        inner_k(dup2(w.z), Us + (kk*4+2)*USTRIDE, acc);
        inner_k(dup2(w.w), Us + (kk*4+3)*USTRIDE, acc);
    }
    float* o = P + ((size_t)split*3072 + v)*32;
    #pragma unroll
    for (int p = 0; p < 16; p++){
        float lo, hi; unpk(acc[p], lo, hi);
        *(float2*)(o + 2*p) = make_float2(lo, hi);
    }
}

// ---------------- 2) GRU activation -> decT[h][b] ----------------
__global__ void k_gru_act(const float* __restrict__ hid,
                          const float* __restrict__ bih, const float* __restrict__ bhh){
    int idx = blockIdx.x*256 + threadIdx.x;  // 32768
    int h = idx >> 5, b = idx & 31;
    float xr=0, xz=0, xn=0, hr=0, hz=0, hn=0;
    #pragma unroll
    for (int s = 0; s < 8; s++){
        size_t base = (size_t)s*3072*32;
        xr += g_xgP[base + (size_t)h*32 + b];
        xz += g_xgP[base + (size_t)(1024+h)*32 + b];
        xn += g_xgP[base + (size_t)(2048+h)*32 + b];
        hr += g_hgP[base + (size_t)h*32 + b];
        hz += g_hgP[base + (size_t)(1024+h)*32 + b];
        hn += g_hgP[base + (size_t)(2048+h)*32 + b];
    }
    xr += bih[h]; xz += bih[1024+h]; xn += bih[2048+h];
    hr += bhh[h]; hz += bhh[1024+h]; hn += bhh[2048+h];
    float r = 1.0f / (1.0f + expf(-(xr + hr)));
    float z = 1.0f / (1.0f + expf(-(xz + hz)));
    float n = tanhf(xn + r*hn);
    float h0 = hid[b*1024 + h];
    g_decT[h*32 + b] = (1.0f - z)*n + z*h0;
}

// ---------------- 3) v gemm: vP[split][e][b] ----------------
// grid (4 eblocks, 32 hsplits), 256 thr
__global__ void __launch_bounds__(256) k_v_gemm(const float* __restrict__ Wattn){
    __shared__ float Us[32*USTRIDE];
    int split = blockIdx.y;
    int k0 = split * 32;
    stage_straight(Us, g_decT + (size_t)k0*32, 32);

    int warp = threadIdx.x >> 5, lane = threadIdx.x & 31;
    int e = blockIdx.x*256 + warp*32 + lane;
    const float* wp = Wattn + (size_t)k0*2048 + 1024 + e;

    u64 acc[16];
    #pragma unroll
    for (int p = 0; p < 16; p++) acc[p] = 0;

    #pragma unroll 8
    for (int k = 0; k < 32; k++){
        float w = wp[(size_t)k*2048];
        inner_k(dup2(w), Us + k*USTRIDE, acc);
    }
    float* o = g_vP + ((size_t)split*1024 + e)*32;
    #pragma unroll
    for (int p = 0; p < 16; p++){
        float lo, hi; unpk(acc[p], lo, hi);
        *(float2*)(o + 2*p) = make_float2(lo, hi);
    }
}

// ---------------- 4) v reduce -> g_v[b][e] ----------------
__global__ void k_v_red(){
    int idx = blockIdx.x*1024 + threadIdx.x;  // 32768
    int e = idx >> 5, b = idx & 31;
    float s = 0.0f;
    #pragma unroll
    for (int c = 0; c < 32; c++) s += g_vP[(size_t)c*32768 + e*32 + b];
    g_v[b*1024 + e] = s;
}

// ---------------- 5) scores[b,s] = enc[s,b,:] . v[b,:] ----------------
__global__ void __launch_bounds__(128) k_scores(const float* __restrict__ enc){
    int g = blockIdx.x * 4 + (threadIdx.x >> 5);
    int lane = threadIdx.x & 31;
    int b = g & 31, s = g >> 5;
    const float4* ep = (const float4*)(enc + (size_t)(s*32 + b)*1024);
    const float4* vp = (const float4*)(g_v + b*1024);
    float acc = 0.0f;
    #pragma unroll
    for (int i = 0; i < 8; i++){
        float4 e4 = ep[i*32 + lane];
        float4 v4 = vp[i*32 + lane];
        acc += e4.x*v4.x + e4.y*v4.y + e4.z*v4.z + e4.w*v4.w;
    }
    #pragma unroll
    for (int off = 16; off; off >>= 1) acc += __shfl_xor_sync(0xFFFFFFFFu, acc, off);
    if (lane == 0) g_scores[b*128 + s] = acc;
}

// ---------------- 6) softmax over s ----------------
__global__ void k_softmax(float* __restrict__ out){
    int b = blockIdx.x, s = threadIdx.x;
    float x = g_scores[b*128 + s];
    __shared__ float red[128];
    red[s] = x; __syncthreads();
    for (int st = 64; st > 0; st >>= 1){ if (s < st) red[s] = fmaxf(red[s], red[s+st]); __syncthreads(); }
    float m = red[0]; __syncthreads();
    float e = expf(x - m);
    red[s] = e; __syncthreads();
    for (int st = 64; st > 0; st >>= 1){ if (s < st) red[s] += red[s+st]; __syncthreads(); }
    float w = e / red[0];
    g_attw[b*128 + s] = w;
    out[(size_t)B_*V_ + b*128 + s] = w;
}

// ---------------- 7) context: ctx[e][b] = sum_s w[b,s]*enc[s,b,e] ----------------
// grid (32 b, 4 e-chunks), 256 thr (thread = e), full s loop (no partials)
__global__ void __launch_bounds__(256) k_context(const float* __restrict__ enc){
    int b = blockIdx.x, ec = blockIdx.y;
    __shared__ float ws[128];
    if (threadIdx.x < 128) ws[threadIdx.x] = g_attw[b*128 + threadIdx.x];
    __syncthreads();
    int e = ec*256 + threadIdx.x;
    const float* ep = enc + (size_t)b*1024 + e;
    float acc = 0.0f;
    #pragma unroll 8
    for (int s = 0; s < 128; s++) acc += ws[s] * ep[(size_t)s*32768];
    g_ctx[e*32 + b] = acc;
}

// ---------------- 8) comb gemm: combP[split][i][b], K=2048 ----------------
// grid (8 vblocks, 16 ksplits), 128 thr
__global__ void __launch_bounds__(128) k_comb_gemm(
    const float* __restrict__ x, const float* __restrict__ Wcomb)
{
    __shared__ float Us[128*USTRIDE];
    int split = blockIdx.y;
    int k0 = split * 128;
    if (split < 8) stage_transpose<128>(Us, x, k0);
    else           stage_straight(Us, g_ctx + (size_t)(k0 - 1024)*32, 128);

    int warp = threadIdx.x >> 5, lane = threadIdx.x & 31;
    int v = blockIdx.x*128 + warp*32 + lane;  // 0..1023
    const float4* w4 = (const float4*)(Wcomb + (size_t)v*2048 + k0);

    u64 acc[16];
    #pragma unroll
    for (int p = 0; p < 16; p++) acc[p] = 0;

    #pragma unroll 4
    for (int kk = 0; kk < 32; kk++){
        float4 w = w4[kk];
        inner_k(dup2(w.x), Us + (kk*4+0)*USTRIDE, acc);
        inner_k(dup2(w.y), Us + (kk*4+1)*USTRIDE, acc);
        inner_k(dup2(w.z), Us + (kk*4+2)*USTRIDE, acc);
        inner_k(dup2(w.w), Us + (kk*4+3)*USTRIDE, acc);
    }
    float* o = g_combP + ((size_t)split*1024 + v)*32;
    #pragma unroll
    for (int p = 0; p < 16; p++){
        float lo, hi; unpk(acc[p], lo, hi);
        *(float2*)(o + 2*p) = make_float2(lo, hi);
    }
}

// ---------------- 9) comb reduce + bias -> outU[k][b] ----------------
__global__ void k_comb_red(const float* __restrict__ bcomb){
    int idx = blockIdx.x*1024 + threadIdx.x;  // 32768
    int k = idx >> 5, b = idx & 31;
    float s = bcomb[k];
    #pragma unroll
    for (int c = 0; c < 16; c++) s += g_combP[(size_t)c*32768 + k*32 + b];
    g_outU[k*32 + b] = s;
}

// ---------------- 10) W_out gemm -> g_logits[b][v] ----------------
// grid 125, 256 thr, 144KB dynamic smem
__global__ void __launch_bounds__(256) k_out_gemm(
    const float* __restrict__ Wout, const float* __restrict__ bout)
{
    extern __shared__ float Us[];  // 1024*USTRIDE
    stage_straight(Us, g_outU, 1024);

    int warp = threadIdx.x >> 5, lane = threadIdx.x & 31;
    int v = blockIdx.x*256 + warp*32 + lane;  // 0..31999
    const float4* w4 = (const float4*)(Wout + (size_t)v*1024);

    u64 acc[16];
    #pragma unroll
    for (int p = 0; p < 16; p++) acc[p] = 0;

    #pragma unroll 2
    for (int kk = 0; kk < 256; kk++){
        float4 w = w4[kk];
        inner_k(dup2(w.x), Us + (kk*4+0)*USTRIDE, acc);
        inner_k(dup2(w.y), Us + (kk*4+1)*USTRIDE, acc);
        inner_k(dup2(w.z), Us + (kk*4+2)*USTRIDE, acc);
        inner_k(dup2(w.w), Us + (kk*4+3)*USTRIDE, acc);
    }
    float bb = bout[v];
    #pragma unroll
    for (int p = 0; p < 16; p++){
        float lo, hi; unpk(acc[p], lo, hi);
        g_logits[(size_t)(2*p  )*V_ + v] = lo + bb;
        g_logits[(size_t)(2*p+1)*V_ + v] = hi + bb;
    }
}

// ---------------- 11) log-softmax partial (online max/sum) ----------------
__global__ void k_lsm_part(){
    int b = blockIdx.x, c = blockIdx.y;
    const float4* base = (const float4*)(g_logits + (size_t)b*V_ + c*4000);
    float m = -3.4e38f, s = 0.0f;
    #pragma unroll
    for (int it = 0; it < 4; it++){
        int idx = threadIdx.x + it*256;
        if (idx < 1000){
            float4 x = base[idx];
            float mx = fmaxf(fmaxf(x.x, x.y), fmaxf(x.z, x.w));
            if (mx > m){ s = s * expf(m - mx); m = mx; }
            s += expf(x.x - m) + expf(x.y - m) + expf(x.z - m) + expf(x.w - m);
        }
    }
    __shared__ float sm[256], ss[256];
    sm[threadIdx.x] = m; ss[threadIdx.x] = s;
    __syncthreads();
    for (int st = 128; st > 0; st >>= 1){
        if (threadIdx.x < st){
            float m2 = sm[threadIdx.x + st], s2 = ss[threadIdx.x + st];
            float mo = fmaxf(sm[threadIdx.x], m2);
            ss[threadIdx.x] = ss[threadIdx.x]*expf(sm[threadIdx.x] - mo) + s2*expf(m2 - mo);
            sm[threadIdx.x] = mo;
        }
        __syncthreads();
    }
    if (threadIdx.x == 0){ g_pm[b*8 + c] = sm[0]; g_ps[b*8 + c] = ss[0]; }
}

// ---------------- 12) log-softmax finalize ----------------
__global__ void k_lsm_write(float* __restrict__ out){
    int b = blockIdx.x;
    float M = -3.4e38f;
    #pragma unroll
    for (int c = 0; c < 8; c++) M = fmaxf(M, g_pm[b*8 + c]);
    float Ssum = 0.0f;
    #pragma unroll
    for (int c = 0; c < 8; c++) Ssum += g_ps[b*8 + c] * expf(g_pm[b*8 + c] - M);
    float off = M + logf(Ssum);

    int chunk = blockIdx.y * 2000;
    const float4* src = (const float4*)(g_logits + (size_t)b*V_ + chunk);
    float4* dst = (float4*)(out + (size_t)b*V_ + chunk);
    #pragma unroll
    for (int it = 0; it < 2; it++){
        int idx = threadIdx.x + it*256;
        if (idx < 500){
            float4 x = src[idx];
            dst[idx] = make_float4(x.x - off, x.y - off, x.z - off, x.w - off);
        }
    }
}

// ---------------- launch ----------------
extern "C" void kernel_launch(void* const* d_in, const int* in_sizes, int n_in,
                              void* d_out, int out_size)
{
    const float* x     = (const float*)d_in[0];
    const float* enc   = (const float*)d_in[1];
    const float* hid   = (const float*)d_in[2];
    const float* Wih   = (const float*)d_in[3];
    const float* Whh   = (const float*)d_in[4];
    const float* bih   = (const float*)d_in[5];
    const float* bhh   = (const float*)d_in[6];
    const float* Wattn = (const float*)d_in[7];
    // d_in[8] = b_attn: softmax-invariant, unused
    const float* Wcomb = (const float*)d_in[9];
    const float* bcomb = (const float*)d_in[10];
    const float* Wout  = (const float*)d_in[11];
    const float* bout  = (const float*)d_in[12];
    float* out = (float*)d_out;

    static bool attr_set = false;
    if (!attr_set){
        cudaFuncSetAttribute(k_out_gemm, cudaFuncAttributeMaxDynamicSharedMemorySize, 1024*USTRIDE*4);
        attr_set = true;
    }

    k_gru_gemm<<<dim3(12, 8, 2), 256>>>(x, hid, Wih, Whh);
    k_gru_act<<<128, 256>>>(hid, bih, bhh);
    k_v_gemm<<<dim3(4, 32), 256>>>(Wattn);
    k_v_red<<<32, 1024>>>();
    k_scores<<<1024, 128>>>(enc);
    k_softmax<<<32, 128>>>(out);
    k_context<<<dim3(32, 4), 256>>>(enc);
    k_comb_gemm<<<dim3(8, 16), 128>>>(x, Wcomb);
    k_comb_red<<<32, 1024>>>(bcomb);
    k_out_gemm<<<125, 256, 1024*USTRIDE*4>>>(Wout, bout);
    k_lsm_part<<<dim3(32, 8), 256>>>();
    k_lsm_write<<<dim3(32, 16), 256>>>(out);
}

// round 4
// speedup vs baseline: 2.1127x; 1.0429x over previous
#include <cuda_runtime.h>
#include <math.h>

#define B_ 32
#define S_ 128
#define V_ 32000
#define NB 148
#define NT 512
#define USTRIDE 36

typedef unsigned long long u64;

// ---------------- scratch ----------------
__device__ __align__(16) float g_gruP[2*8*3072*32];   // [mat][kc][row][b]
__device__ __align__(16) float g_decT[1024*32];       // [h][b]
__device__ __align__(16) float g_vP[32*1024*32];      // [kc][e][b]
__device__ __align__(16) float g_v[32*1024];          // [b][e]
__device__ __align__(16) float g_scores[32*128];
__device__ __align__(16) float g_attw[32*128];
__device__ __align__(16) float g_ctx[1024*32];        // [e][b]
__device__ __align__(16) float g_combP[32*1024*32];   // [kc][i][b]
__device__ __align__(16) float g_outU[1024*32];       // [k][b]
__device__ __align__(16) float g_P0[32*32000];        // logits partial kh=0 [b][v]
__device__ __align__(16) float g_P1[32*32000];        // logits partial kh=1 [b][v]
__device__ float g_pm[256], g_ps[256], g_off[32];

// ---------------- grid barrier (148 blocks, all resident: 1 block/SM) ----------------
__device__ unsigned g_bar_cnt;
__device__ volatile unsigned g_bar_gen;

__device__ __forceinline__ void gsync(){
    __syncthreads();
    if (threadIdx.x == 0){
        unsigned target = g_bar_gen + 1u;   // relative: survives graph replays
        __threadfence();
        if (atomicAdd(&g_bar_cnt, 1u) == NB - 1u){
            g_bar_cnt = 0u;
            __threadfence();
            g_bar_gen = target;
        } else {
            while ((int)(g_bar_gen - target) < 0) __nanosleep(64);
            __threadfence();
        }
    }
    __syncthreads();
}

// ---------------- f32x2 helpers ----------------
#define FMA2(acc,a,b) asm("fma.rn.f32x2 %0, %1, %2, %0;" : "+l"(acc) : "l"(a), "l"(b))
__device__ __forceinline__ u64 dup2(float w){ u64 r; asm("mov.b64 %0, {%1, %1};" : "=l"(r) : "f"(w)); return r; }
__device__ __forceinline__ u64 d2u(double d){ return (u64)__double_as_longlong(d); }
__device__ __forceinline__ void unpk(u64 v, float& a, float& b){ asm("mov.b64 {%0,%1}, %2;" : "=f"(a), "=f"(b) : "l"(v)); }

__device__ __forceinline__ void inner_k(u64 wd, const float* Usk, u64 acc[16]){
    #pragma unroll
    for (int p = 0; p < 16; p += 2){
        double2 u2 = *(const double2*)(Usk + 2*p);   // broadcast LDS.128
        FMA2(acc[p],   wd, d2u(u2.x));
        FMA2(acc[p+1], wd, d2u(u2.y));
    }
}

__device__ __forceinline__ void st_pairs(float* o, const u64 acc[16]){
    #pragma unroll
    for (int p = 0; p < 16; p++){
        float lo, hi; unpk(acc[p], lo, hi);
        *(float2*)(o + 2*p) = make_float2(lo, hi);
    }
}

// ================= fused kernel =================
__global__ void __launch_bounds__(NT, 1) k_fused(
    const float* __restrict__ x, const float* __restrict__ enc,
    const float* __restrict__ hid,
    const float* __restrict__ Wih, const float* __restrict__ Whh,
    const float* __restrict__ bih, const float* __restrict__ bhh,
    const float* __restrict__ Wattn,
    const float* __restrict__ Wcomb, const float* __restrict__ bcomb,
    const float* __restrict__ Wout, const float* __restrict__ bout,
    float* __restrict__ out)
{
    extern __shared__ float smU[];
    const int bid = blockIdx.x, tid = threadIdx.x;
    const int wid = tid >> 5, lane = tid & 31;
    const int gtid = bid * NT + tid;
    const int gw = bid * 16 + wid;

    // ---- S0: GRU gemm partials (144 blocks: 2 mats x 8 kchunks x 9 vblocks) ----
    if (bid < 144){
        int mat = bid / 72, r = bid % 72;
        int kc = r / 9, vb = r % 9;
        int v0 = vb * 342;
        int nv = (vb == 8) ? 336 : 342;
        const float* W  = mat ? Whh : Wih;
        const float* src = mat ? hid : x;
        int k0 = kc * 128;
        for (int idx = tid; idx < 128*32; idx += NT){
            int b = idx >> 7, kk = idx & 127;
            smU[kk*USTRIDE + b] = src[b*1024 + k0 + kk];
        }
        __syncthreads();
        if (tid < nv){
            int v = v0 + tid;
            const float4* w4 = (const float4*)(W + (size_t)v*1024 + k0);
            u64 acc[16];
            #pragma unroll
            for (int p = 0; p < 16; p++) acc[p] = 0;
            #pragma unroll 4
            for (int kk = 0; kk < 32; kk++){
                float4 w = w4[kk];
                inner_k(dup2(w.x), smU + (kk*4+0)*USTRIDE, acc);
                inner_k(dup2(w.y), smU + (kk*4+1)*USTRIDE, acc);
                inner_k(dup2(w.z), smU + (kk*4+2)*USTRIDE, acc);
                inner_k(dup2(w.w), smU + (kk*4+3)*USTRIDE, acc);
            }
            st_pairs(g_gruP + ((size_t)(mat*8+kc)*3072 + v)*32, acc);
        }
    }
    gsync();

    // ---- S1: GRU activation -> decT[h][b] ----
    if (gtid < 32768){
        int h = gtid >> 5, b = gtid & 31;
        float s0=0,s1=0,s2=0,s3=0,s4=0,s5=0;
        #pragma unroll
        for (int kc = 0; kc < 8; kc++){
            const float* Pa = g_gruP + (size_t)kc*3072*32;
            const float* Pb = g_gruP + (size_t)(8+kc)*3072*32;
            s0 += Pa[(size_t)h*32+b];
            s1 += Pa[(size_t)(1024+h)*32+b];
            s2 += Pa[(size_t)(2048+h)*32+b];
            s3 += Pb[(size_t)h*32+b];
            s4 += Pb[(size_t)(1024+h)*32+b];
            s5 += Pb[(size_t)(2048+h)*32+b];
        }
        float xr=s0+bih[h], xz=s1+bih[1024+h], xn=s2+bih[2048+h];
        float hr=s3+bhh[h], hz=s4+bhh[1024+h], hn=s5+bhh[2048+h];
        float rr = 1.0f/(1.0f+expf(-(xr+hr)));
        float zz = 1.0f/(1.0f+expf(-(xz+hz)));
        float nn = tanhf(xn + rr*hn);
        g_decT[h*32+b] = (1.0f-zz)*nn + zz*hid[b*1024+h];
    }
    gsync();

    // ---- S2: v gemm partials (128 blocks: kc=bid>>2 of 32k, e-chunk=(bid&3)*256) ----
    if (bid < 128){
        int kc = bid >> 2, e0 = (bid & 3) * 256;
        int k0 = kc * 32;
        for (int idx = tid; idx < 1024; idx += NT){
            int k = idx >> 5, b = idx & 31;
            smU[k*USTRIDE + b] = g_decT[(k0+k)*32 + b];
        }
        __syncthreads();
        if (tid < 256){
            int e = e0 + tid;
            const float* wp = Wattn + (size_t)k0*2048 + 1024 + e;
            u64 acc[16];
            #pragma unroll
            for (int p = 0; p < 16; p++) acc[p] = 0;
            #pragma unroll 8
            for (int k = 0; k < 32; k++)
                inner_k(dup2(wp[(size_t)k*2048]), smU + k*USTRIDE, acc);
            st_pairs(g_vP + ((size_t)kc*1024 + e)*32, acc);
        }
    }
    gsync();

    // ---- S3: v reduce -> g_v[b][e] ----
    if (gtid < 32768){
        int e = gtid >> 5, b = gtid & 31;
        float s = 0.0f;
        #pragma unroll
        for (int kc = 0; kc < 32; kc++) s += g_vP[((size_t)kc*1024 + e)*32 + b];
        g_v[b*1024 + e] = s;
    }
    gsync();

    // ---- S4: scores[b][s] = enc[s,b,:].v[b,:] (warp units, grid-stride) ----
    for (int u = gw; u < 4096; u += NB*16){
        int b = u & 31, s = u >> 5;
        const float4* ep = (const float4*)(enc + (size_t)(s*32+b)*1024);
        const float4* vp = (const float4*)(g_v + b*1024);
        float a = 0.0f;
        #pragma unroll
        for (int i = 0; i < 8; i++){
            float4 e4 = ep[i*32 + lane];
            float4 v4 = vp[i*32 + lane];
            a += e4.x*v4.x + e4.y*v4.y + e4.z*v4.z + e4.w*v4.w;
        }
        #pragma unroll
        for (int o = 16; o; o >>= 1) a += __shfl_xor_sync(0xFFFFFFFFu, a, o);
        if (lane == 0) g_scores[b*128 + s] = a;
    }
    gsync();

    // ---- S5: softmax over s (warp per b) + write attn weights to out tail ----
    if (gw < 32){
        int b = gw;
        float v0 = g_scores[b*128 + lane];
        float v1 = g_scores[b*128 + 32 + lane];
        float v2 = g_scores[b*128 + 64 + lane];
        float v3 = g_scores[b*128 + 96 + lane];
        float m = fmaxf(fmaxf(v0,v1), fmaxf(v2,v3));
        #pragma unroll
        for (int o = 16; o; o >>= 1) m = fmaxf(m, __shfl_xor_sync(0xFFFFFFFFu, m, o));
        float e0 = expf(v0-m), e1 = expf(v1-m), e2 = expf(v2-m), e3 = expf(v3-m);
        float s = e0+e1+e2+e3;
        #pragma unroll
        for (int o = 16; o; o >>= 1) s += __shfl_xor_sync(0xFFFFFFFFu, s, o);
        float inv = 1.0f / s;
        float w0 = e0*inv, w1 = e1*inv, w2 = e2*inv, w3 = e3*inv;
        g_attw[b*128 + lane]      = w0;  out[(size_t)B_*V_ + b*128 + lane]      = w0;
        g_attw[b*128 + 32 + lane] = w1;  out[(size_t)B_*V_ + b*128 + 32 + lane] = w1;
        g_attw[b*128 + 64 + lane] = w2;  out[(size_t)B_*V_ + b*128 + 64 + lane] = w2;
        g_attw[b*128 + 96 + lane] = w3;  out[(size_t)B_*V_ + b*128 + 96 + lane] = w3;
    }
    gsync();

    // ---- S6: context ctx[e][b] = sum_s w[b,s] enc[s,b,e] ----
    if (gtid < 32768){
        int b = gtid >> 10, e = gtid & 1023;
        const float* ep = enc + (size_t)b*1024 + e;
        const float* wsp = g_attw + b*128;
        float a = 0.0f;
        #pragma unroll 8
        for (int s = 0; s < 128; s++) a += wsp[s] * ep[(size_t)s*32768];
        g_ctx[e*32 + b] = a;
    }
    gsync();

    // ---- S7: comb gemm partials (128 blocks: kc=bid>>2 of 64k, i-chunk=(bid&3)*256) ----
    if (bid < 128){
        int kc = bid >> 2, i0 = (bid & 3) * 256;
        int k0 = kc * 64;
        if (kc < 16){
            for (int idx = tid; idx < 2048; idx += NT){
                int b = idx >> 6, kk = idx & 63;
                smU[kk*USTRIDE + b] = x[b*1024 + k0 + kk];
            }
        } else {
            for (int idx = tid; idx < 2048; idx += NT){
                int kk = idx >> 5, b = idx & 31;
                smU[kk*USTRIDE + b] = g_ctx[(k0 - 1024 + kk)*32 + b];
            }
        }
        __syncthreads();
        if (tid < 256){
            int i = i0 + tid;
            const float4* w4 = (const float4*)(Wcomb + (size_t)i*2048 + k0);
            u64 acc[16];
            #pragma unroll
            for (int p = 0; p < 16; p++) acc[p] = 0;
            #pragma unroll 4
            for (int kk = 0; kk < 16; kk++){
                float4 w = w4[kk];
                inner_k(dup2(w.x), smU + (kk*4+0)*USTRIDE, acc);
                inner_k(dup2(w.y), smU + (kk*4+1)*USTRIDE, acc);
                inner_k(dup2(w.z), smU + (kk*4+2)*USTRIDE, acc);
                inner_k(dup2(w.w), smU + (kk*4+3)*USTRIDE, acc);
            }
            st_pairs(g_combP + ((size_t)kc*1024 + i)*32, acc);
        }
    }
    gsync();

    // ---- S8: comb reduce + bias -> outU[k][b] ----
    if (gtid < 32768){
        int k = gtid >> 5, b = gtid & 31;
        float s = bcomb[k];
        #pragma unroll
        for (int kc = 0; kc < 32; kc++) s += g_combP[((size_t)kc*1024 + k)*32 + b];
        g_outU[k*32 + b] = s;
    }
    gsync();

    // ---- S9: W_out gemm (warp-units: 1000 vchunks x 2 khalves, bid-interleaved) ----
    {
        for (int idx = tid; idx < 8192; idx += NT){
            int k = idx >> 3, q = idx & 7;
            *(float4*)(smU + k*USTRIDE + q*4) = ((const float4*)g_outU)[idx];
        }
        __syncthreads();
        int wu = bid + NB*wid;
        if (wu < 2000){
            int vc = wu % 1000, kh = wu / 1000;
            int v = vc*32 + lane;
            const float4* w4 = (const float4*)(Wout + (size_t)v*1024 + kh*512);
            const float* Ub = smU + (kh*512)*USTRIDE;
            u64 acc[16];
            #pragma unroll
            for (int p = 0; p < 16; p++) acc[p] = 0;
            #pragma unroll 2
            for (int kk = 0; kk < 128; kk++){
                float4 w = w4[kk];
                inner_k(dup2(w.x), Ub + (kk*4+0)*USTRIDE, acc);
                inner_k(dup2(w.y), Ub + (kk*4+1)*USTRIDE, acc);
                inner_k(dup2(w.z), Ub + (kk*4+2)*USTRIDE, acc);
                inner_k(dup2(w.w), Ub + (kk*4+3)*USTRIDE, acc);
            }
            float bb = (kh == 0) ? bout[v] : 0.0f;
            float* P = kh ? g_P1 : g_P0;
            #pragma unroll
            for (int p = 0; p < 16; p++){
                float lo, hi; unpk(acc[p], lo, hi);
                P[(size_t)(2*p  )*V_ + v] = lo + bb;
                P[(size_t)(2*p+1)*V_ + v] = hi + bb;
            }
        }
    }
    gsync();

    // ---- S10: log-softmax partials per (b, chunk of 4000) ----
    if (gw < 256){
        int b = gw >> 3, c = gw & 7;
        const float* p0 = g_P0 + (size_t)b*V_ + c*4000;
        const float* p1 = g_P1 + (size_t)b*V_ + c*4000;
        float m = -3.4e38f, s = 0.0f;
        for (int j = 0; j < 125; j++){
            float val = p0[j*32 + lane] + p1[j*32 + lane];
            if (val > m){ s *= expf(m - val); m = val; }
            s += expf(val - m);
        }
        #pragma unroll
        for (int o = 16; o; o >>= 1){
            float m2 = __shfl_xor_sync(0xFFFFFFFFu, m, o);
            float s2 = __shfl_xor_sync(0xFFFFFFFFu, s, o);
            float mo = fmaxf(m, m2);
            s = s*expf(m - mo) + s2*expf(m2 - mo);
            m = mo;
        }
        if (lane == 0){ g_pm[gw] = m; g_ps[gw] = s; }
    }
    gsync();

    // ---- S11: combine per-b -> off[b] ----
    if (gtid < 32){
        float M = -3.4e38f;
        #pragma unroll
        for (int c = 0; c < 8; c++) M = fmaxf(M, g_pm[gtid*8 + c]);
        float S = 0.0f;
        #pragma unroll
        for (int c = 0; c < 8; c++) S += g_ps[gtid*8 + c] * expf(g_pm[gtid*8 + c] - M);
        g_off[gtid] = M + logf(S);
    }
    gsync();

    // ---- S12: final write out[b][v] = P0+P1-off ----
    for (int u = gtid; u < 256000; u += NB*NT){
        int b = u / 8000, r = u - b*8000;
        float4 a = ((const float4*)(g_P0 + (size_t)b*V_))[r];
        float4 c = ((const float4*)(g_P1 + (size_t)b*V_))[r];
        float off = g_off[b];
        ((float4*)(out + (size_t)b*V_))[r] =
            make_float4(a.x+c.x-off, a.y+c.y-off, a.z+c.z-off, a.w+c.w-off);
    }
}

// ---------------- launch ----------------
extern "C" void kernel_launch(void* const* d_in, const int* in_sizes, int n_in,
                              void* d_out, int out_size)
{
    const float* x     = (const float*)d_in[0];
    const float* enc   = (const float*)d_in[1];
    const float* hid   = (const float*)d_in[2];
    const float* Wih   = (const float*)d_in[3];
    const float* Whh   = (const float*)d_in[4];
    const float* bih   = (const float*)d_in[5];
    const float* bhh   = (const float*)d_in[6];
    const float* Wattn = (const float*)d_in[7];
    // d_in[8] = b_attn: softmax-invariant, unused
    const float* Wcomb = (const float*)d_in[9];
    const float* bcomb = (const float*)d_in[10];
    const float* Wout  = (const float*)d_in[11];
    const float* bout  = (const float*)d_in[12];
    float* out = (float*)d_out;

    static bool once = false;
    if (!once){
        cudaFuncSetAttribute(k_fused, cudaFuncAttributeMaxDynamicSharedMemorySize, 1024*USTRIDE*4);
        once = true;
    }
    k_fused<<<NB, NT, 1024*USTRIDE*4>>>(x, enc, hid, Wih, Whh, bih, bhh,
                                        Wattn, Wcomb, bcomb, Wout, bout, out);
}

// round 5
// speedup vs baseline: 2.2474x; 1.0638x over previous
#include <cuda_runtime.h>
#include <math.h>

#define B_ 32
#define S_ 128
#define V_ 32000
#define NB 148
#define NT 512
#define USTRIDE 36

typedef unsigned long long u64;

// ---------------- scratch ----------------
__device__ __align__(16) float g_gruP[8*3072*32];     // [mat*4+kc][row][b]
__device__ __align__(16) float g_decT[1024*32];       // [h][b]
__device__ __align__(16) float g_vP[32*1024*32];      // [kc][e][b]
__device__ __align__(16) float g_v[32*1024];          // [b][e]
__device__ __align__(16) float g_scores[32*128];
__device__ __align__(16) float g_attw[32*128];
__device__ __align__(16) float g_ctx[1024*32];        // [e][b]
__device__ __align__(16) float g_combP[32*1024*32];   // [kc][i][b]
__device__ __align__(16) float g_outU[1024*32];       // [k][b]
__device__ __align__(16) float g_logits[32*32000];    // [b][v]
__device__ float g_pm[256], g_ps[256], g_off[32];

// ---------------- grid barrier (148 blocks, all resident) ----------------
__device__ unsigned g_bar_cnt;
__device__ volatile unsigned g_bar_gen;

__device__ __forceinline__ void gsync(){
    __syncthreads();
    if (threadIdx.x == 0){
        unsigned target = g_bar_gen + 1u;
        __threadfence();
        if (atomicAdd(&g_bar_cnt, 1u) == NB - 1u){
            g_bar_cnt = 0u;
            __threadfence();
            g_bar_gen = target;
        } else {
            while ((int)(g_bar_gen - target) < 0) __nanosleep(64);
            __threadfence();
        }
    }
    __syncthreads();
}

// ---------------- f32x2 helpers ----------------
#define FMA2(acc,a,b) asm("fma.rn.f32x2 %0, %1, %2, %0;" : "+l"(acc) : "l"(a), "l"(b))
__device__ __forceinline__ u64 dup2(float w){ u64 r; asm("mov.b64 %0, {%1, %1};" : "=l"(r) : "f"(w)); return r; }
__device__ __forceinline__ u64 d2u(double d){ return (u64)__double_as_longlong(d); }
__device__ __forceinline__ void unpk(u64 v, float& a, float& b){ asm("mov.b64 {%0,%1}, %2;" : "=f"(a), "=f"(b) : "l"(v)); }

__device__ __forceinline__ void inner_k(u64 wd, const float* Usk, u64 acc[16]){
    #pragma unroll
    for (int p = 0; p < 16; p += 2){
        double2 u2 = *(const double2*)(Usk + 2*p);   // broadcast LDS.128 (2-phase when lanes split k)
        FMA2(acc[p],   wd, d2u(u2.x));
        FMA2(acc[p+1], wd, d2u(u2.y));
    }
}

// process one float4 (4 consecutive k starting at kbase)
__device__ __forceinline__ void proc4(float4 w, const float* U0, u64 acc[16]){
    inner_k(dup2(w.x), U0,             acc);
    inner_k(dup2(w.y), U0 + USTRIDE,   acc);
    inner_k(dup2(w.z), U0 + 2*USTRIDE, acc);
    inner_k(dup2(w.w), U0 + 3*USTRIDE, acc);
}

// merge lane pairs (even/odd k halves) and store 32 b values; even lane writes
__device__ __forceinline__ void merge_store_pairs(u64 acc[16], float* o, int par){
    #pragma unroll
    for (int p = 0; p < 16; p++){
        float lo, hi; unpk(acc[p], lo, hi);
        lo += __shfl_xor_sync(0xFFFFFFFFu, lo, 1);
        hi += __shfl_xor_sync(0xFFFFFFFFu, hi, 1);
        if (par == 0) *(float2*)(o + 2*p) = make_float2(lo, hi);
    }
}

// ================= fused kernel =================
__global__ void __launch_bounds__(NT, 1) k_fused(
    const float* __restrict__ x, const float* __restrict__ enc,
    const float* __restrict__ hid,
    const float* __restrict__ Wih, const float* __restrict__ Whh,
    const float* __restrict__ bih, const float* __restrict__ bhh,
    const float* __restrict__ Wattn,
    const float* __restrict__ Wcomb, const float* __restrict__ bcomb,
    const float* __restrict__ Wout, const float* __restrict__ bout,
    float* __restrict__ out)
{
    extern __shared__ float smU[];
    const int bid = blockIdx.x, tid = threadIdx.x;
    const int wid = tid >> 5, lane = tid & 31;
    const int gtid = bid * NT + tid;
    const int gw = bid * 16 + wid;
    const int par = lane & 1;

    // ---- S0: GRU gemm partials (128 blocks: 2 mats x 4 kchunks(256) x 16 vblocks(192 rows)) ----
    if (bid < 128){
        int mat = bid >> 6, r = bid & 63;
        int kc = r >> 4, vb = r & 15;
        const float* W   = mat ? Whh : Wih;
        const float* src = mat ? hid : x;
        int k0 = kc * 256;
        for (int idx = tid; idx < 256*32; idx += NT){
            int b = idx >> 8, kk = idx & 255;
            smU[kk*USTRIDE + b] = src[b*1024 + k0 + kk];
        }
        __syncthreads();
        if (tid < 384){
            int row = vb*192 + (tid >> 1);
            const float4* w4 = (const float4*)(W + (size_t)row*1024 + k0) + par;
            u64 acc[16];
            #pragma unroll
            for (int p = 0; p < 16; p++) acc[p] = 0;
            float4 buf[4];
            #pragma unroll
            for (int p = 0; p < 4; p++) buf[p] = w4[2*p];
            for (int j = 0; j < 32; j += 4){
                float4 c0 = buf[0], c1 = buf[1], c2 = buf[2], c3 = buf[3];
                if (j + 4 < 32){
                    #pragma unroll
                    for (int p = 0; p < 4; p++) buf[p] = w4[2*(j+4+p)];
                }
                proc4(c0, smU + (8*(j+0)+4*par)*USTRIDE, acc);
                proc4(c1, smU + (8*(j+1)+4*par)*USTRIDE, acc);
                proc4(c2, smU + (8*(j+2)+4*par)*USTRIDE, acc);
                proc4(c3, smU + (8*(j+3)+4*par)*USTRIDE, acc);
            }
            merge_store_pairs(acc, g_gruP + ((size_t)(mat*4+kc)*3072 + row)*32, par);
        }
    }
    gsync();

    // ---- S1: GRU activation -> decT[h][b] ----
    if (gtid < 32768){
        int h = gtid >> 5, b = gtid & 31;
        float s0=0,s1=0,s2=0,s3=0,s4=0,s5=0;
        #pragma unroll
        for (int kc = 0; kc < 4; kc++){
            const float* Pa = g_gruP + (size_t)kc*3072*32;
            const float* Pb = g_gruP + (size_t)(4+kc)*3072*32;
            s0 += Pa[(size_t)h*32+b];
            s1 += Pa[(size_t)(1024+h)*32+b];
            s2 += Pa[(size_t)(2048+h)*32+b];
            s3 += Pb[(size_t)h*32+b];
            s4 += Pb[(size_t)(1024+h)*32+b];
            s5 += Pb[(size_t)(2048+h)*32+b];
        }
        float xr=s0+bih[h], xz=s1+bih[1024+h], xn=s2+bih[2048+h];
        float hr=s3+bhh[h], hz=s4+bhh[1024+h], hn=s5+bhh[2048+h];
        float rr = 1.0f/(1.0f+expf(-(xr+hr)));
        float zz = 1.0f/(1.0f+expf(-(xz+hz)));
        float nn = tanhf(xn + rr*hn);
        g_decT[h*32+b] = (1.0f-zz)*nn + zz*hid[b*1024+h];
    }
    gsync();

    // ---- S2: v gemm partials (128 blocks: kc of 32k x 4 e-chunks; W e-contiguous=coalesced) ----
    if (bid < 128){
        int kc = bid >> 2, e0 = (bid & 3) * 256;
        int k0 = kc * 32;
        for (int idx = tid; idx < 1024; idx += NT){
            int k = idx >> 5, b = idx & 31;
            smU[k*USTRIDE + b] = g_decT[(k0+k)*32 + b];
        }
        __syncthreads();
        if (tid < 256){
            int e = e0 + tid;
            const float* wp = Wattn + (size_t)k0*2048 + 1024 + e;
            u64 acc[16];
            #pragma unroll
            for (int p = 0; p < 16; p++) acc[p] = 0;
            #pragma unroll 8
            for (int k = 0; k < 32; k++)
                inner_k(dup2(wp[(size_t)k*2048]), smU + k*USTRIDE, acc);
            float* o = g_vP + ((size_t)kc*1024 + e)*32;
            #pragma unroll
            for (int p = 0; p < 16; p++){
                float lo, hi; unpk(acc[p], lo, hi);
                *(float2*)(o + 2*p) = make_float2(lo, hi);
            }
        }
    }
    gsync();

    // ---- S3: v reduce -> g_v[b][e] ----
    if (gtid < 32768){
        int e = gtid >> 5, b = gtid & 31;
        float s = 0.0f;
        #pragma unroll
        for (int kc = 0; kc < 32; kc++) s += g_vP[((size_t)kc*1024 + e)*32 + b];
        g_v[b*1024 + e] = s;
    }
    gsync();

    // ---- S4: scores[b][s] = enc[s,b,:].v[b,:] ----
    for (int u = gw; u < 4096; u += NB*16){
        int b = u & 31, s = u >> 5;
        const float4* ep = (const float4*)(enc + (size_t)(s*32+b)*1024);
        const float4* vp = (const float4*)(g_v + b*1024);
        float a = 0.0f;
        #pragma unroll
        for (int i = 0; i < 8; i++){
            float4 e4 = ep[i*32 + lane];
            float4 v4 = vp[i*32 + lane];
            a += e4.x*v4.x + e4.y*v4.y + e4.z*v4.z + e4.w*v4.w;
        }
        #pragma unroll
        for (int o = 16; o; o >>= 1) a += __shfl_xor_sync(0xFFFFFFFFu, a, o);
        if (lane == 0) g_scores[b*128 + s] = a;
    }
    gsync();

    // ---- S5: softmax over s (warp per b) + attn weights to out tail ----
    if (gw < 32){
        int b = gw;
        float v0 = g_scores[b*128 + lane];
        float v1 = g_scores[b*128 + 32 + lane];
        float v2 = g_scores[b*128 + 64 + lane];
        float v3 = g_scores[b*128 + 96 + lane];
        float m = fmaxf(fmaxf(v0,v1), fmaxf(v2,v3));
        #pragma unroll
        for (int o = 16; o; o >>= 1) m = fmaxf(m, __shfl_xor_sync(0xFFFFFFFFu, m, o));
        float e0 = expf(v0-m), e1 = expf(v1-m), e2 = expf(v2-m), e3 = expf(v3-m);
        float s = e0+e1+e2+e3;
        #pragma unroll
        for (int o = 16; o; o >>= 1) s += __shfl_xor_sync(0xFFFFFFFFu, s, o);
        float inv = 1.0f / s;
        float w0 = e0*inv, w1 = e1*inv, w2 = e2*inv, w3 = e3*inv;
        g_attw[b*128 + lane]      = w0;  out[(size_t)B_*V_ + b*128 + lane]      = w0;
        g_attw[b*128 + 32 + lane] = w1;  out[(size_t)B_*V_ + b*128 + 32 + lane] = w1;
        g_attw[b*128 + 64 + lane] = w2;  out[(size_t)B_*V_ + b*128 + 64 + lane] = w2;
        g_attw[b*128 + 96 + lane] = w3;  out[(size_t)B_*V_ + b*128 + 96 + lane] = w3;
    }
    gsync();

    // ---- S6: context ctx[e][b] = sum_s w[b,s] enc[s,b,e] ----
    if (gtid < 32768){
        int b = gtid >> 10, e = gtid & 1023;
        const float* ep = enc + (size_t)b*1024 + e;
        const float* wsp = g_attw + b*128;
        float a = 0.0f;
        #pragma unroll 8
        for (int s = 0; s < 128; s++) a += wsp[s] * ep[(size_t)s*32768];
        g_ctx[e*32 + b] = a;
    }
    gsync();

    // ---- S7: comb gemm partials (128 blocks: kc of 64k x 4 i-chunks(256 rows), lane-paired) ----
    if (bid < 128){
        int kc = bid >> 2, i0 = (bid & 3) * 256;
        int k0 = kc * 64;
        if (kc < 16){
            for (int idx = tid; idx < 64*32; idx += NT){
                int b = idx >> 6, kk = idx & 63;
                smU[kk*USTRIDE + b] = x[b*1024 + k0 + kk];
            }
        } else {
            for (int idx = tid; idx < 64*32; idx += NT){
                int kk = idx >> 5, b = idx & 31;
                smU[kk*USTRIDE + b] = g_ctx[(k0 - 1024 + kk)*32 + b];
            }
        }
        __syncthreads();
        {
            int row = i0 + (tid >> 1);
            const float4* w4 = (const float4*)(Wcomb + (size_t)row*2048 + k0) + par;
            u64 acc[16];
            #pragma unroll
            for (int p = 0; p < 16; p++) acc[p] = 0;
            float4 buf[4];
            #pragma unroll
            for (int p = 0; p < 4; p++) buf[p] = w4[2*p];
            #pragma unroll
            for (int j = 0; j < 8; j += 4){
                float4 c0 = buf[0], c1 = buf[1], c2 = buf[2], c3 = buf[3];
                if (j + 4 < 8){
                    #pragma unroll
                    for (int p = 0; p < 4; p++) buf[p] = w4[2*(j+4+p)];
                }
                proc4(c0, smU + (8*(j+0)+4*par)*USTRIDE, acc);
                proc4(c1, smU + (8*(j+1)+4*par)*USTRIDE, acc);
                proc4(c2, smU + (8*(j+2)+4*par)*USTRIDE, acc);
                proc4(c3, smU + (8*(j+3)+4*par)*USTRIDE, acc);
            }
            merge_store_pairs(acc, g_combP + ((size_t)kc*1024 + row)*32, par);
        }
    }
    gsync();

    // ---- S8: comb reduce + bias -> outU[k][b] ----
    if (gtid < 32768){
        int k = gtid >> 5, b = gtid & 31;
        float s = bcomb[k];
        #pragma unroll
        for (int kc = 0; kc < 32; kc++) s += g_combP[((size_t)kc*1024 + k)*32 + b];
        g_outU[k*32 + b] = s;
    }
    gsync();

    // ---- S9: W_out gemm (2000 warp-units x 16 rows, lane-paired k, full K=1024) ----
    {
        for (int idx = tid; idx < 8192; idx += NT){
            int k = idx >> 3, q = idx & 7;
            *(float4*)(smU + k*USTRIDE + q*4) = ((const float4*)g_outU)[idx];
        }
        __syncthreads();
        int wu = bid + NB*wid;
        if (wu < 2000){
            int row = wu*16 + (lane >> 1);
            const float4* w4 = (const float4*)(Wout + (size_t)row*1024) + par;
            u64 acc[16];
            #pragma unroll
            for (int p = 0; p < 16; p++) acc[p] = 0;
            float4 buf[4];
            #pragma unroll
            for (int p = 0; p < 4; p++) buf[p] = w4[2*p];
            for (int j = 0; j < 128; j += 4){
                float4 c0 = buf[0], c1 = buf[1], c2 = buf[2], c3 = buf[3];
                if (j + 4 < 128){
                    #pragma unroll
                    for (int p = 0; p < 4; p++) buf[p] = w4[2*(j+4+p)];
                }
                proc4(c0, smU + (8*(j+0)+4*par)*USTRIDE, acc);
                proc4(c1, smU + (8*(j+1)+4*par)*USTRIDE, acc);
                proc4(c2, smU + (8*(j+2)+4*par)*USTRIDE, acc);
                proc4(c3, smU + (8*(j+3)+4*par)*USTRIDE, acc);
            }
            float bb = bout[row];
            #pragma unroll
            for (int p = 0; p < 16; p++){
                float lo, hi; unpk(acc[p], lo, hi);
                lo += __shfl_xor_sync(0xFFFFFFFFu, lo, 1);
                hi += __shfl_xor_sync(0xFFFFFFFFu, hi, 1);
                if (par == 0){
                    g_logits[(size_t)(2*p  )*V_ + row] = lo + bb;
                    g_logits[(size_t)(2*p+1)*V_ + row] = hi + bb;
                }
            }
        }
    }
    gsync();

    // ---- S10: log-softmax partials per (b, chunk of 4000) ----
    if (gw < 256){
        int b = gw >> 3, c = gw & 7;
        const float* p0 = g_logits + (size_t)b*V_ + c*4000;
        float m = -3.4e38f, s = 0.0f;
        for (int j = 0; j < 125; j++){
            float val = p0[j*32 + lane];
            if (val > m){ s *= expf(m - val); m = val; }
            s += expf(val - m);
        }
        #pragma unroll
        for (int o = 16; o; o >>= 1){
            float m2 = __shfl_xor_sync(0xFFFFFFFFu, m, o);
            float s2 = __shfl_xor_sync(0xFFFFFFFFu, s, o);
            float mo = fmaxf(m, m2);
            s = s*expf(m - mo) + s2*expf(m2 - mo);
            m = mo;
        }
        if (lane == 0){ g_pm[gw] = m; g_ps[gw] = s; }
    }
    gsync();

    // ---- S11: combine per-b -> off[b] ----
    if (gtid < 32){
        float M = -3.4e38f;
        #pragma unroll
        for (int c = 0; c < 8; c++) M = fmaxf(M, g_pm[gtid*8 + c]);
        float S = 0.0f;
        #pragma unroll
        for (int c = 0; c < 8; c++) S += g_ps[gtid*8 + c] * expf(g_pm[gtid*8 + c] - M);
        g_off[gtid] = M + logf(S);
    }
    gsync();

    // ---- S12: final write out[b][v] = logits - off ----
    for (int u = gtid; u < 256000; u += NB*NT){
        int b = u / 8000, r = u - b*8000;
        float4 a = ((const float4*)(g_logits + (size_t)b*V_))[r];
        float off = g_off[b];
        ((float4*)(out + (size_t)b*V_))[r] =
            make_float4(a.x-off, a.y-off, a.z-off, a.w-off);
    }
}

// ---------------- launch ----------------
extern "C" void kernel_launch(void* const* d_in, const int* in_sizes, int n_in,
                              void* d_out, int out_size)
{
    const float* x     = (const float*)d_in[0];
    const float* enc   = (const float*)d_in[1];
    const float* hid   = (const float*)d_in[2];
    const float* Wih   = (const float*)d_in[3];
    const float* Whh   = (const float*)d_in[4];
    const float* bih   = (const float*)d_in[5];
    const float* bhh   = (const float*)d_in[6];
    const float* Wattn = (const float*)d_in[7];
    // d_in[8] = b_attn: softmax-invariant, unused
    const float* Wcomb = (const float*)d_in[9];
    const float* bcomb = (const float*)d_in[10];
    const float* Wout  = (const float*)d_in[11];
    const float* bout  = (const float*)d_in[12];
    float* out = (float*)d_out;

    static bool once = false;
    if (!once){
        cudaFuncSetAttribute(k_fused, cudaFuncAttributeMaxDynamicSharedMemorySize, 1024*USTRIDE*4);
        once = true;
    }
    k_fused<<<NB, NT, 1024*USTRIDE*4>>>(x, enc, hid, Wih, Whh, bih, bhh,
                                        Wattn, Wcomb, bcomb, Wout, bout, out);
}